// round 16
// baseline (speedup 1.0000x reference)
#include <cuda_runtime.h>
#include <cuda_bf16.h>
#include <cstdint>

#define GN    8192
#define LMBD  0.1f
#define QCAP  64
#define QEFF  (QCAP - 4)
#define FULLM 0xffffffffu

__device__ float    g_sum;     // zero-init; reset by last block each launch
__device__ unsigned g_count;
__device__ __align__(16) __nv_bfloat162 g_Wbf[GN * 64];   // bf16(W), 2MB

__device__ __forceinline__ void cpa16(uint32_t dst_smem, const void* src) {
    asm volatile("cp.async.cg.shared.global [%0], [%1], 16;"
                 :: "r"(dst_smem), "l"(src));
}
__device__ __forceinline__ __nv_bfloat162 asbf2(unsigned u) {
    __nv_bfloat162 h; *reinterpret_cast<unsigned*>(&h) = u; return h;
}

// ---------------------------------------------------------------------------
// Prep: W (f32) -> g_Wbf (bf16). 2 float4 per thread, one uint4 store.
// ---------------------------------------------------------------------------
__global__ void prep_bf16(const float* __restrict__ W) {
    int i = blockIdx.x * 256 + threadIdx.x;          // 131072 threads
    const float4* W4 = reinterpret_cast<const float4*>(W);
    float4 a = W4[i * 2], c = W4[i * 2 + 1];
    __nv_bfloat162 r0 = __floats2bfloat162_rn(a.x, a.y);
    __nv_bfloat162 r1 = __floats2bfloat162_rn(a.z, a.w);
    __nv_bfloat162 r2 = __floats2bfloat162_rn(c.x, c.y);
    __nv_bfloat162 r3 = __floats2bfloat162_rn(c.z, c.w);
    uint4 o;
    o.x = *reinterpret_cast<unsigned*>(&r0);
    o.y = *reinterpret_cast<unsigned*>(&r1);
    o.z = *reinterpret_cast<unsigned*>(&r2);
    o.w = *reinterpret_cast<unsigned*>(&r3);
    reinterpret_cast<uint4*>(g_Wbf)[i] = o;
}

// ---------------------------------------------------------------------------
// R14 structure (best: 62.2us), W dot reads in bf16: one LDG.128 per lane per
// entry (256B/row), 4x HFMA2 bf16x2 accumulate, f32 4-shfl reduce.
// One block per row (8192 x 256). Warp w owns cols [w*1024,(w+1)*1024).
// A staged via 2x 2KB cp.async commit groups. Compact: 1 ballot/float4,
// first nz queued as (a, j*16) float2; extras/overflow one deferred ballot
// per half, slow path reloads A from the stage. pred = Wbf[j].yi_bf + ci.
// ---------------------------------------------------------------------------
__global__ void __launch_bounds__(256, 6)
main_kernel(const float* __restrict__ A, const float* __restrict__ W,
            const float* __restrict__ b, float* __restrict__ out) {
    __shared__ float4 stage[8][256];   // 8 warps x 4KB
    __shared__ float2 q[8][QCAP];      // (a, bits(j*16))
    __shared__ float  sp[8];

    const int row  = blockIdx.x;
    const int w    = threadIdx.x >> 5;
    const int lane = threadIdx.x & 31;
    const int hl   = lane & 15;    // lane within 16-lane group
    const int grp  = lane >> 4;    // group 0..1
    const unsigned ltm = (1u << lane) - 1u;

    const float4* __restrict__ A4 =
        reinterpret_cast<const float4*>(A) + (size_t)row * (GN / 4);
    const float4* __restrict__ W4 = reinterpret_cast<const float4*>(W);
    const float4* __restrict__ B4 = reinterpret_cast<const float4*>(b);
    const uint4*  __restrict__ WB = reinterpret_cast<const uint4*>(g_Wbf);

    const int base4 = w * 256;

    // L2 loads FIRST (drain early from the in-order L1tex queue) ...
    // lane hl holds elems [8*hl, 8*hl+8) = float4 indices {2hl, 2hl+1}
    float4 wv0 = W4[row * 32 + 2 * hl];
    float4 wv1 = W4[row * 32 + 2 * hl + 1];
    float4 bv0 = B4[2 * hl];
    float4 bv1 = B4[2 * hl + 1];

    // ... then stream the 4KB A segment as TWO 2KB commit groups
    {
        uint32_t sdst = (uint32_t)__cvta_generic_to_shared(&stage[w][lane]);
        const float4* gsrc = A4 + base4 + lane;
        #pragma unroll
        for (int k = 0; k < 4; k++) cpa16(sdst + k * 512, gsrc + k * 32);
        asm volatile("cp.async.commit_group;");
        #pragma unroll
        for (int k = 4; k < 8; k++) cpa16(sdst + k * 512, gsrc + k * 32);
        asm volatile("cp.async.commit_group;");
    }

    // yi = W[row]+b; ci = b.yi (4-shfl chain); rn folded per-lane (no chain).
    float acc = 0.f;
    __nv_bfloat162 ybf0, ybf1, ybf2, ybf3;
    float ci;
    {
        float4 yi0, yi1;
        yi0.x = wv0.x + bv0.x; yi0.y = wv0.y + bv0.y;
        yi0.z = wv0.z + bv0.z; yi0.w = wv0.w + bv0.w;
        yi1.x = wv1.x + bv1.x; yi1.y = wv1.y + bv1.y;
        yi1.z = wv1.z + bv1.z; yi1.w = wv1.w + bv1.w;
        ci = bv0.x*yi0.x + bv0.y*yi0.y + bv0.z*yi0.z + bv0.w*yi0.w
           + bv1.x*yi1.x + bv1.y*yi1.y + bv1.z*yi1.z + bv1.w*yi1.w;
        #pragma unroll
        for (int off = 1; off < 16; off <<= 1)
            ci += __shfl_xor_sync(FULLM, ci, off);

        if (w == 0 && lane < 16) {   // reg loss: per-lane, summed at the end
            float rl = yi0.x*yi0.x + yi0.y*yi0.y + yi0.z*yi0.z + yi0.w*yi0.w
                     + yi1.x*yi1.x + yi1.y*yi1.y + yi1.z*yi1.z + yi1.w*yi1.w;
            acc = 0.5f * LMBD * rl;
        }
        ybf0 = __floats2bfloat162_rn(yi0.x, yi0.y);
        ybf1 = __floats2bfloat162_rn(yi0.z, yi0.w);
        ybf2 = __floats2bfloat162_rn(yi1.x, yi1.y);
        ybf3 = __floats2bfloat162_rn(yi1.z, yi1.w);
    }

    // 16-lane-group dot vs bf16 W row (z = 4 bf16x2 = 8 elems per lane)
    auto dotbf = [&](uint4 z) -> float {
        __nv_bfloat162 h = __hmul2(asbf2(z.x), ybf0);
        h = __hfma2(asbf2(z.y), ybf1, h);
        h = __hfma2(asbf2(z.z), ybf2, h);
        h = __hfma2(asbf2(z.w), ybf3, h);
        float p = __low2float(h) + __high2float(h);
        p += __shfl_xor_sync(FULLM, p, 1);
        p += __shfl_xor_sync(FULLM, p, 2);
        p += __shfl_xor_sync(FULLM, p, 4);
        p += __shfl_xor_sync(FULLM, p, 8);
        return p;
    };

    int cnt = 0;   // warp-uniform

    // compact 4 float4 groups [kbase, kbase+4); extras/overflow deferred to
    // ONE ballot per half; slow path reloads A from the smem stage.
    auto compact_half = [&](int kbase) {
        unsigned exm = 0u;   // 4 bits per k-slot: extra-component masks
        unsigned ovm = 0u;   // 1 bit per k-slot: overflow
        #pragma unroll
        for (int kk = 0; kk < 4; kk++) {
            const int k = kbase + kk;
            float4 a4 = stage[w][k * 32 + lane];
            unsigned nzm = (a4.x > 0.f ? 1u : 0u) | (a4.y > 0.f ? 2u : 0u)
                         | (a4.z > 0.f ? 4u : 0u) | (a4.w > 0.f ? 8u : 0u);
            bool nz = nzm != 0u;
            unsigned m = __ballot_sync(FULLM, nz);
            if (m) {
                int e0 = __ffs(nzm) - 1;
                float a0 = (e0 <= 0) ? a4.x : (e0 == 1) ? a4.y
                         : (e0 == 2) ? a4.z : a4.w;
                int pos = cnt + __popc(m & ltm);
                bool ovf = nz && pos >= QEFF;
                if (nz && !ovf) {
                    int j = (base4 + k * 32 + lane) * 4 + e0;
                    q[w][pos] = make_float2(a0, __int_as_float(j * 16));
                }
                exm |= (nz ? (nzm & (nzm - 1u)) : 0u) << (kk * 4);
                if (ovf) ovm |= 1u << kk;
                cnt = min(cnt + __popc(m), QEFF);
            }
        }
        unsigned mo = __ballot_sync(FULLM, (exm | ovm) != 0u);
        while (mo) {   // rare (P ~ 1% per warp-half)
            int src = __ffs(mo) - 1; mo &= mo - 1;
            unsigned sex = __shfl_sync(FULLM, exm, src);
            unsigned sov = __shfl_sync(FULLM, ovm, src);
            #pragma unroll
            for (int kk = 0; kk < 4; kk++) {
                unsigned tk = (sex >> (kk * 4)) & 0xFu;
                if (sov & (1u << kk)) tk = 0xFu;   // overflow: redo float4
                if (tk) {
                    const int k = kbase + kk;
                    float4 a4 = stage[w][k * 32 + src];   // reload, no shfl
                    int jb = (base4 + k * 32 + src) * 4;
                    while (tk) {
                        int e = __ffs(tk) - 1; tk &= tk - 1;
                        float a = (e == 0) ? a4.x : (e == 1) ? a4.y
                                : (e == 2) ? a4.z : a4.w;
                        if (a > 0.f) {
                            float p = dotbf(WB[(jb + e) * 16 + hl]);
                            if (lane == 0) {
                                float rr = a - (p + ci);
                                acc = fmaf(0.5f * rr, rr, acc);
                            }
                        }
                    }
                }
            }
        }
    };

    // first half ready -> compact while second half still streams in
    asm volatile("cp.async.wait_group 1;");
    __syncwarp();
    compact_half(0);
    asm volatile("cp.async.wait_group 0;");
    __syncwarp();
    compact_half(4);

    // single drain: 4 entries per iteration, both W-loads before any reduce
    {
        int cntp = (cnt + 3) & ~3;
        if (lane < cntp - cnt) q[w][cnt + lane] = make_float2(0.f, 0.f);
        __syncwarp();
        for (int base = 0; base < cntp; base += 4) {
            float2 eA = q[w][base + grp];       // 1x LDS.64 each
            float2 eB = q[w][base + 2 + grp];
            int jA16 = __float_as_int(eA.y);
            int jB16 = __float_as_int(eB.y);
            uint4 za = WB[jA16 + hl];           // one LDG.128 per entry-lane
            uint4 zb = WB[jB16 + hl];
            float pA = dotbf(za);
            if (eA.x > 0.f && hl == 0) {
                float rr = eA.x - (pA + ci);
                acc = fmaf(0.5f * rr, rr, acc);
            }
            float pB = dotbf(zb);
            if (eB.x > 0.f && hl == 0) {
                float rr = eB.x - (pB + ci);
                acc = fmaf(0.5f * rr, rr, acc);
            }
        }
    }

    // block reduce (sums per-lane rl partials + per-group dot partials)
    #pragma unroll
    for (int off = 16; off > 0; off >>= 1)
        acc += __shfl_xor_sync(FULLM, acc, off);
    if (lane == 0) sp[w] = acc;
    __syncthreads();

    if (threadIdx.x == 0) {
        float part = 0.f;
        #pragma unroll
        for (int i = 0; i < 8; i++) part += sp[i];
        atomicAdd(&g_sum, part);
        __threadfence();
        unsigned c = atomicAdd(&g_count, 1u);
        if (c == gridDim.x - 1) {
            float total = atomicExch(&g_sum, 0.f);
            atomicExch(&g_count, 0u);
            out[0] = total;
        }
    }
}

extern "C" void kernel_launch(void* const* d_in, const int* in_sizes, int n_in,
                              void* d_out, int out_size) {
    const float* A = (const float*)d_in[0];
    const float* W = (const float*)d_in[1];
    const float* b = (const float*)d_in[2];
    float* out = (float*)d_out;

    prep_bf16<<<512, 256>>>(W);
    main_kernel<<<GN, 256>>>(A, W, b, out);
}